// round 1
// baseline (speedup 1.0000x reference)
#include <cuda_runtime.h>
#include <cuda_bf16.h>
#include <math.h>

#define NSEG 8192
#define HDIM 512
#define MAXE 262144

// ---------------- device scratch (no allocations allowed) ----------------
__device__ float g_xl[NSEG * HDIM];
__device__ float g_xr[NSEG * HDIM];
__device__ float g_buf0[NSEG * HDIM];
__device__ float g_buf1[NSEG * HDIM];
__device__ float g_e[MAXE];
__device__ float g_alpha[MAXE];
__device__ int   g_cnt[NSEG];
__device__ int   g_rowptr[NSEG + 1];
__device__ int   g_cursor[NSEG];
__device__ int   g_ceid[MAXE];
__device__ int   g_csrc[MAXE];

// ---------------- GEMM: Y = X @ W + b (row-major), z-dim picks (Wl,bl,xl)/(Wr,br,xr) ----------------
#define BM 128
#define BN 128
#define BK 8
#define TM 8
#define TN 8

__global__ __launch_bounds__(256, 2)
void gemm_bias_kernel(const float* __restrict__ X,
                      const float* __restrict__ W0, const float* __restrict__ b0, float* __restrict__ Y0,
                      const float* __restrict__ W1, const float* __restrict__ b1, float* __restrict__ Y1,
                      int M, int N, int K)
{
    const float* W    = blockIdx.z ? W1 : W0;
    const float* bias = blockIdx.z ? b1 : b0;
    float*       Y    = blockIdx.z ? Y1 : Y0;

    __shared__ float As[BK][BM];
    __shared__ float Bs[BK][BN];

    const int tid = threadIdx.x;            // 0..255
    const int tx = tid % 16, ty = tid / 16; // 16x16 thread grid, 8x8 microtile
    const int rowBase = blockIdx.y * BM;
    const int colBase = blockIdx.x * BN;

    // A tile: 128 rows x 8 k -> 256 float4, one per thread
    const int aRow  = tid >> 1;        // 0..127
    const int aCol4 = (tid & 1) * 4;   // 0 or 4
    // B tile: 8 k x 128 cols -> 256 float4
    const int bRow  = tid >> 5;        // 0..7
    const int bCol4 = (tid & 31) * 4;  // 0..124

    float acc[TM][TN];
#pragma unroll
    for (int i = 0; i < TM; i++)
#pragma unroll
        for (int j = 0; j < TN; j++) acc[i][j] = 0.f;

    const float* Aptr = X + (size_t)rowBase * K;
    const float* Bptr = W + colBase;

    for (int k0 = 0; k0 < K; k0 += BK) {
        float4 av = *(const float4*)(Aptr + (size_t)aRow * K + k0 + aCol4);
        As[aCol4 + 0][aRow] = av.x;
        As[aCol4 + 1][aRow] = av.y;
        As[aCol4 + 2][aRow] = av.z;
        As[aCol4 + 3][aRow] = av.w;
        float4 bv = *(const float4*)(Bptr + (size_t)(k0 + bRow) * N + bCol4);
        *(float4*)&Bs[bRow][bCol4] = bv;
        __syncthreads();

#pragma unroll
        for (int k = 0; k < BK; k++) {
            float af[TM], bf[TN];
#pragma unroll
            for (int i = 0; i < TM; i++) af[i] = As[k][ty * TM + i];
#pragma unroll
            for (int j = 0; j < TN; j++) bf[j] = Bs[k][tx * TN + j];
#pragma unroll
            for (int i = 0; i < TM; i++)
#pragma unroll
                for (int j = 0; j < TN; j++)
                    acc[i][j] = fmaf(af[i], bf[j], acc[i][j]);
        }
        __syncthreads();
    }

#pragma unroll
    for (int i = 0; i < TM; i++) {
        const int r = rowBase + ty * TM + i;
#pragma unroll
        for (int j = 0; j < TN; j += 4) {
            const int c = colBase + tx * TN + j;
            float4 v;
            v.x = acc[i][j + 0] + bias[c + 0];
            v.y = acc[i][j + 1] + bias[c + 1];
            v.z = acc[i][j + 2] + bias[c + 2];
            v.w = acc[i][j + 3] + bias[c + 3];
            *(float4*)(Y + (size_t)r * N + c) = v;
        }
    }
}

// ---------------- CSR build (by dst) ----------------
__global__ void zero_cnt_kernel(int* __restrict__ cnt) {
    int i = blockIdx.x * blockDim.x + threadIdx.x;
    if (i < NSEG) cnt[i] = 0;
}

__global__ void hist_kernel(const int* __restrict__ dst, int* __restrict__ cnt, int E) {
    int k = blockIdx.x * blockDim.x + threadIdx.x;
    if (k < E) atomicAdd(&cnt[dst[k]], 1);
}

__global__ void scan8192_kernel(const int* __restrict__ cnt, int* __restrict__ rowptr,
                                int* __restrict__ cursor)
{
    __shared__ int sums[1024];
    const int t = threadIdx.x;           // 1024 threads, 8 items each
    const int base = t * 8;
    int local[8];
    int s = 0;
#pragma unroll
    for (int j = 0; j < 8; j++) { local[j] = s; s += cnt[base + j]; }
    sums[t] = s;
    __syncthreads();
    for (int off = 1; off < 1024; off <<= 1) {
        int v = (t >= off) ? sums[t - off] : 0;
        __syncthreads();
        sums[t] += v;
        __syncthreads();
    }
    const int excl = (t == 0) ? 0 : sums[t - 1];
#pragma unroll
    for (int j = 0; j < 8; j++) {
        int v = excl + local[j];
        rowptr[base + j] = v;
        cursor[base + j] = v;
    }
    if (t == 1023) rowptr[NSEG] = sums[1023];
}

__global__ void scatter_kernel(const int* __restrict__ src, const int* __restrict__ dst,
                               int* __restrict__ cursor, int* __restrict__ ceid,
                               int* __restrict__ csrc, int E)
{
    int k = blockIdx.x * blockDim.x + threadIdx.x;
    if (k < E) {
        int p = atomicAdd(&cursor[dst[k]], 1);
        ceid[p] = k;
        csrc[p] = src[k];
    }
}

// ---------------- edge score: e[k] = a . leaky_relu(xl[src] + xr[dst]) ----------------
__device__ __forceinline__ float lrelu(float v) { return v > 0.f ? v : 0.2f * v; }

__global__ __launch_bounds__(256)
void edge_score_kernel(const float* __restrict__ xl, const float* __restrict__ xr,
                       const float* __restrict__ a,
                       const int* __restrict__ src, const int* __restrict__ dst,
                       float* __restrict__ e, int E)
{
    const int warp = (blockIdx.x * blockDim.x + threadIdx.x) >> 5;
    const int lane = threadIdx.x & 31;
    if (warp >= E) return;
    const int s = src[warp], d = dst[warp];
    const float4* xl4 = (const float4*)(xl + (size_t)s * HDIM);
    const float4* xr4 = (const float4*)(xr + (size_t)d * HDIM);
    const float4* a4  = (const float4*)a;
    float acc = 0.f;
#pragma unroll
    for (int i = 0; i < HDIM / 128; i++) {      // 4 iterations of float4 per lane
        const int idx = i * 32 + lane;
        float4 u = xl4[idx], v = xr4[idx], w = a4[idx];
        acc = fmaf(w.x, lrelu(u.x + v.x), acc);
        acc = fmaf(w.y, lrelu(u.y + v.y), acc);
        acc = fmaf(w.z, lrelu(u.z + v.z), acc);
        acc = fmaf(w.w, lrelu(u.w + v.w), acc);
    }
#pragma unroll
    for (int off = 16; off; off >>= 1) acc += __shfl_xor_sync(0xFFFFFFFFu, acc, off);
    if (lane == 0) e[warp] = acc;
}

// ---------------- per-dst segment softmax over CSR (warp per node) ----------------
__global__ __launch_bounds__(256)
void softmax_kernel(const float* __restrict__ e, const int* __restrict__ rowptr,
                    const int* __restrict__ ceid, float* __restrict__ alpha)
{
    const int node = (blockIdx.x * blockDim.x + threadIdx.x) >> 5;
    const int lane = threadIdx.x & 31;
    if (node >= NSEG) return;
    const int s0 = rowptr[node], s1 = rowptr[node + 1];
    if (s0 == s1) return;
    float m = -INFINITY;
    for (int j = s0 + lane; j < s1; j += 32) m = fmaxf(m, e[ceid[j]]);
#pragma unroll
    for (int off = 16; off; off >>= 1) m = fmaxf(m, __shfl_xor_sync(0xFFFFFFFFu, m, off));
    float sum = 0.f;
    for (int j = s0 + lane; j < s1; j += 32) sum += expf(e[ceid[j]] - m);
#pragma unroll
    for (int off = 16; off; off >>= 1) sum += __shfl_xor_sync(0xFFFFFFFFu, sum, off);
    const float inv = 1.f / sum;
    for (int j = s0 + lane; j < s1; j += 32) alpha[j] = expf(e[ceid[j]] - m) * inv;
}

// ---------------- per-dst aggregation: out[i] = sum_j alpha_j * xl[src_j] + bias ----------------
__global__ __launch_bounds__(128)
void aggregate_kernel(const float* __restrict__ xl, const float* __restrict__ alpha,
                      const int* __restrict__ rowptr, const int* __restrict__ csrc,
                      const float* __restrict__ bias, float* __restrict__ out)
{
    const int node = blockIdx.x;
    const int t = threadIdx.x;               // 128 threads * float4 = 512
    const int s0 = rowptr[node], s1 = rowptr[node + 1];
    float4 acc = ((const float4*)bias)[t];
    for (int j = s0; j < s1; j++) {
        const float w = alpha[j];
        const float4 v = ((const float4*)(xl + (size_t)csrc[j] * HDIM))[t];
        acc.x = fmaf(w, v.x, acc.x);
        acc.y = fmaf(w, v.y, acc.y);
        acc.z = fmaf(w, v.z, acc.z);
        acc.w = fmaf(w, v.w, acc.w);
    }
    ((float4*)(out + (size_t)node * HDIM))[t] = acc;
}

// ---------------- launch ----------------
extern "C" void kernel_launch(void* const* d_in, const int* in_sizes, int n_in,
                              void* d_out, int out_size)
{
    const float* x0   = (const float*)d_in[0];
    const int*   eidx = (const int*)d_in[2];
    const int    E    = in_sizes[2] / 2;
    float*       out  = (float*)d_out;

    const int* src = eidx;
    const int* dst = eidx + E;

    float *xl, *xr, *b0, *b1, *e, *alpha;
    int *cnt, *rowptr, *cursor, *ceid, *csrc;
    cudaGetSymbolAddress((void**)&xl,     g_xl);
    cudaGetSymbolAddress((void**)&xr,     g_xr);
    cudaGetSymbolAddress((void**)&b0,     g_buf0);
    cudaGetSymbolAddress((void**)&b1,     g_buf1);
    cudaGetSymbolAddress((void**)&e,      g_e);
    cudaGetSymbolAddress((void**)&alpha,  g_alpha);
    cudaGetSymbolAddress((void**)&cnt,    g_cnt);
    cudaGetSymbolAddress((void**)&rowptr, g_rowptr);
    cudaGetSymbolAddress((void**)&cursor, g_cursor);
    cudaGetSymbolAddress((void**)&ceid,   g_ceid);
    cudaGetSymbolAddress((void**)&csrc,   g_csrc);

    // CSR by dst (built fresh every launch; edge set is identical across layers)
    zero_cnt_kernel<<<(NSEG + 255) / 256, 256>>>(cnt);
    hist_kernel<<<(E + 255) / 256, 256>>>(dst, cnt, E);
    scan8192_kernel<<<1, 1024>>>(cnt, rowptr, cursor);
    scatter_kernel<<<(E + 255) / 256, 256>>>(src, dst, cursor, ceid, csrc, E);

    const float* xin = x0;
    float* outs[3] = { b0, b1, out };
    for (int L = 0; L < 3; L++) {
        const int base = 3 + 6 * L;
        const float* Wl   = (const float*)d_in[base + 0];
        const float* bl   = (const float*)d_in[base + 1];
        const float* Wr   = (const float*)d_in[base + 2];
        const float* br   = (const float*)d_in[base + 3];
        const float* avec = (const float*)d_in[base + 4];
        const float* bias = (const float*)d_in[base + 5];

        dim3 gg(HDIM / BN, NSEG / BM, 2);
        gemm_bias_kernel<<<gg, 256>>>(xin, Wl, bl, xl, Wr, br, xr, NSEG, HDIM, HDIM);
        edge_score_kernel<<<(E + 7) / 8, 256>>>(xl, xr, avec, src, dst, e, E);
        softmax_kernel<<<(NSEG + 7) / 8, 256>>>(e, rowptr, ceid, alpha);
        aggregate_kernel<<<NSEG, 128>>>(xl, alpha, rowptr, csrc, bias, outs[L]);

        xin = outs[L];
    }
}

// round 2
// speedup vs baseline: 2.2677x; 2.2677x over previous
#include <cuda_runtime.h>
#include <cuda_bf16.h>
#include <math.h>

#define NSEG 8192
#define HDIM 512
#define MAXE 262144

// ---------------- device scratch (no allocations allowed) ----------------
__device__ float g_xl[NSEG * HDIM];
__device__ float g_xr[NSEG * HDIM];
__device__ float g_buf0[NSEG * HDIM];
__device__ float g_buf1[NSEG * HDIM];
__device__ float g_e[MAXE];
__device__ float g_alpha[MAXE];
__device__ int   g_cnt[NSEG];
__device__ int   g_rowptr[NSEG + 1];
__device__ int   g_cursor[NSEG];
__device__ int   g_ceid[MAXE];
__device__ int   g_csrc[MAXE];

__device__ __forceinline__ float to_tf32(float x) {
    float r;
    asm("cvt.rna.tf32.f32 %0, %1;" : "=f"(r) : "f"(x));
    return r;
}

// ---------------- tf32 tensor-core GEMM: Y = X @ W + b, z picks (Wl)/(Wr) ----------------
// M=8192, N=512, K=512 fixed. BM=128 BN=128 BK=32, 8 warps (2x4), warp tile 64x32.
__global__ __launch_bounds__(256, 2)
void gemm_tf32_kernel(const float* __restrict__ X,
                      const float* __restrict__ W0, const float* __restrict__ b0, float* __restrict__ Y0,
                      const float* __restrict__ W1, const float* __restrict__ b1, float* __restrict__ Y1)
{
    const float* W    = blockIdx.z ? W1 : W0;
    const float* bias = blockIdx.z ? b1 : b0;
    float*       Y    = blockIdx.z ? Y1 : Y0;

    __shared__ float As[128][36];   // [m][k] pad->conflict-free a-frag LDS
    __shared__ float Bs[32][136];   // [k][n] pad->conflict-free b-frag LDS

    const int tid  = threadIdx.x;
    const int lane = tid & 31;
    const int warp = tid >> 5;
    const int warpR = warp & 1;          // 0..1 -> 64-row slab
    const int warpC = warp >> 1;         // 0..3 -> 32-col slab

    const int rowBase = blockIdx.y * 128;
    const int colBase = blockIdx.x * 128;

    const int qr = lane >> 2;  // lane/4 : 0..7
    const int qc = lane & 3;   // lane%4 : 0..3

    float acc[4][4][4];
#pragma unroll
    for (int i = 0; i < 4; i++)
#pragma unroll
        for (int j = 0; j < 4; j++)
#pragma unroll
            for (int r = 0; r < 4; r++) acc[i][j][r] = 0.f;

    // global-load assignments
    const int aR = tid >> 3;            // 0..31, step 32 (x4)
    const int aC = (tid & 7) * 4;       // 0..28
    const int bR = tid >> 5;            // 0..7, step 8 (x4)
    const int bC = (tid & 31) * 4;      // 0..124

    for (int kb = 0; kb < 16; kb++) {
        const int k0g = kb * 32;
#pragma unroll
        for (int i = 0; i < 4; i++) {
            const int r = aR + i * 32;
            float4 v = *(const float4*)(X + (size_t)(rowBase + r) * 512 + k0g + aC);
            As[r][aC + 0] = to_tf32(v.x);
            As[r][aC + 1] = to_tf32(v.y);
            As[r][aC + 2] = to_tf32(v.z);
            As[r][aC + 3] = to_tf32(v.w);
        }
#pragma unroll
        for (int i = 0; i < 4; i++) {
            const int r = bR + i * 8;
            float4 v = *(const float4*)(W + (size_t)(k0g + r) * 512 + colBase + bC);
            Bs[r][bC + 0] = to_tf32(v.x);
            Bs[r][bC + 1] = to_tf32(v.y);
            Bs[r][bC + 2] = to_tf32(v.z);
            Bs[r][bC + 3] = to_tf32(v.w);
        }
        __syncthreads();

#pragma unroll
        for (int ks = 0; ks < 4; ks++) {
            const int k0 = ks * 8;
            unsigned a[4][4], b[4][2];
#pragma unroll
            for (int mt = 0; mt < 4; mt++) {
                const int m0 = warpR * 64 + mt * 16;
                a[mt][0] = __float_as_uint(As[m0 + qr    ][k0 + qc    ]);
                a[mt][1] = __float_as_uint(As[m0 + qr + 8][k0 + qc    ]);
                a[mt][2] = __float_as_uint(As[m0 + qr    ][k0 + qc + 4]);
                a[mt][3] = __float_as_uint(As[m0 + qr + 8][k0 + qc + 4]);
            }
#pragma unroll
            for (int nt = 0; nt < 4; nt++) {
                const int n0 = warpC * 32 + nt * 8;
                b[nt][0] = __float_as_uint(Bs[k0 + qc    ][n0 + qr]);
                b[nt][1] = __float_as_uint(Bs[k0 + qc + 4][n0 + qr]);
            }
#pragma unroll
            for (int mt = 0; mt < 4; mt++)
#pragma unroll
                for (int nt = 0; nt < 4; nt++) {
                    asm volatile(
                        "mma.sync.aligned.m16n8k8.row.col.f32.tf32.tf32.f32 "
                        "{%0,%1,%2,%3}, {%4,%5,%6,%7}, {%8,%9}, {%0,%1,%2,%3};"
                        : "+f"(acc[mt][nt][0]), "+f"(acc[mt][nt][1]),
                          "+f"(acc[mt][nt][2]), "+f"(acc[mt][nt][3])
                        : "r"(a[mt][0]), "r"(a[mt][1]), "r"(a[mt][2]), "r"(a[mt][3]),
                          "r"(b[nt][0]), "r"(b[nt][1]));
                }
        }
        __syncthreads();
    }

    // epilogue: + bias, store float2 pairs
#pragma unroll
    for (int mt = 0; mt < 4; mt++) {
#pragma unroll
        for (int nt = 0; nt < 4; nt++) {
            const int col = colBase + warpC * 32 + nt * 8 + qc * 2;
            const float bx = bias[col], by = bias[col + 1];
            const int r0 = rowBase + warpR * 64 + mt * 16 + qr;
            float2 v0 = make_float2(acc[mt][nt][0] + bx, acc[mt][nt][1] + by);
            float2 v1 = make_float2(acc[mt][nt][2] + bx, acc[mt][nt][3] + by);
            *(float2*)(Y + (size_t)r0 * 512 + col)       = v0;
            *(float2*)(Y + (size_t)(r0 + 8) * 512 + col) = v1;
        }
    }
}

// ---------------- CSR build (by dst) ----------------
__global__ void zero_cnt_kernel(int* __restrict__ cnt) {
    int i = blockIdx.x * blockDim.x + threadIdx.x;
    if (i < NSEG) cnt[i] = 0;
}

__global__ void hist_kernel(const int* __restrict__ dst, int* __restrict__ cnt, int E) {
    int k = blockIdx.x * blockDim.x + threadIdx.x;
    if (k < E) atomicAdd(&cnt[dst[k]], 1);
}

__global__ void scan8192_kernel(const int* __restrict__ cnt, int* __restrict__ rowptr,
                                int* __restrict__ cursor)
{
    __shared__ int sums[1024];
    const int t = threadIdx.x;
    const int base = t * 8;
    int local[8];
    int s = 0;
#pragma unroll
    for (int j = 0; j < 8; j++) { local[j] = s; s += cnt[base + j]; }
    sums[t] = s;
    __syncthreads();
    for (int off = 1; off < 1024; off <<= 1) {
        int v = (t >= off) ? sums[t - off] : 0;
        __syncthreads();
        sums[t] += v;
        __syncthreads();
    }
    const int excl = (t == 0) ? 0 : sums[t - 1];
#pragma unroll
    for (int j = 0; j < 8; j++) {
        int v = excl + local[j];
        rowptr[base + j] = v;
        cursor[base + j] = v;
    }
    if (t == 1023) rowptr[NSEG] = sums[1023];
}

__global__ void scatter_kernel(const int* __restrict__ src, const int* __restrict__ dst,
                               int* __restrict__ cursor, int* __restrict__ ceid,
                               int* __restrict__ csrc, int E)
{
    int k = blockIdx.x * blockDim.x + threadIdx.x;
    if (k < E) {
        int p = atomicAdd(&cursor[dst[k]], 1);
        ceid[p] = k;
        csrc[p] = src[k];
    }
}

// ---------------- edge score ----------------
__device__ __forceinline__ float lrelu(float v) { return v > 0.f ? v : 0.2f * v; }

__global__ __launch_bounds__(256)
void edge_score_kernel(const float* __restrict__ xl, const float* __restrict__ xr,
                       const float* __restrict__ a,
                       const int* __restrict__ src, const int* __restrict__ dst,
                       float* __restrict__ e, int E)
{
    const int warp = (blockIdx.x * blockDim.x + threadIdx.x) >> 5;
    const int lane = threadIdx.x & 31;
    if (warp >= E) return;
    const int s = src[warp], d = dst[warp];
    const float4* xl4 = (const float4*)(xl + (size_t)s * HDIM);
    const float4* xr4 = (const float4*)(xr + (size_t)d * HDIM);
    const float4* a4  = (const float4*)a;
    float acc = 0.f;
#pragma unroll
    for (int i = 0; i < HDIM / 128; i++) {
        const int idx = i * 32 + lane;
        float4 u = xl4[idx], v = xr4[idx], w = a4[idx];
        acc = fmaf(w.x, lrelu(u.x + v.x), acc);
        acc = fmaf(w.y, lrelu(u.y + v.y), acc);
        acc = fmaf(w.z, lrelu(u.z + v.z), acc);
        acc = fmaf(w.w, lrelu(u.w + v.w), acc);
    }
#pragma unroll
    for (int off = 16; off; off >>= 1) acc += __shfl_xor_sync(0xFFFFFFFFu, acc, off);
    if (lane == 0) e[warp] = acc;
}

// ---------------- per-dst segment softmax ----------------
__global__ __launch_bounds__(256)
void softmax_kernel(const float* __restrict__ e, const int* __restrict__ rowptr,
                    const int* __restrict__ ceid, float* __restrict__ alpha)
{
    const int node = (blockIdx.x * blockDim.x + threadIdx.x) >> 5;
    const int lane = threadIdx.x & 31;
    if (node >= NSEG) return;
    const int s0 = rowptr[node], s1 = rowptr[node + 1];
    if (s0 == s1) return;
    float m = -INFINITY;
    for (int j = s0 + lane; j < s1; j += 32) m = fmaxf(m, e[ceid[j]]);
#pragma unroll
    for (int off = 16; off; off >>= 1) m = fmaxf(m, __shfl_xor_sync(0xFFFFFFFFu, m, off));
    float sum = 0.f;
    for (int j = s0 + lane; j < s1; j += 32) sum += expf(e[ceid[j]] - m);
#pragma unroll
    for (int off = 16; off; off >>= 1) sum += __shfl_xor_sync(0xFFFFFFFFu, sum, off);
    const float inv = 1.f / sum;
    for (int j = s0 + lane; j < s1; j += 32) alpha[j] = expf(e[ceid[j]] - m) * inv;
}

// ---------------- per-dst aggregation ----------------
__global__ __launch_bounds__(128)
void aggregate_kernel(const float* __restrict__ xl, const float* __restrict__ alpha,
                      const int* __restrict__ rowptr, const int* __restrict__ csrc,
                      const float* __restrict__ bias, float* __restrict__ out)
{
    const int node = blockIdx.x;
    const int t = threadIdx.x;
    const int s0 = rowptr[node], s1 = rowptr[node + 1];
    float4 acc = ((const float4*)bias)[t];
    for (int j = s0; j < s1; j++) {
        const float w = alpha[j];
        const float4 v = ((const float4*)(xl + (size_t)csrc[j] * HDIM))[t];
        acc.x = fmaf(w, v.x, acc.x);
        acc.y = fmaf(w, v.y, acc.y);
        acc.z = fmaf(w, v.z, acc.z);
        acc.w = fmaf(w, v.w, acc.w);
    }
    ((float4*)(out + (size_t)node * HDIM))[t] = acc;
}

// ---------------- launch ----------------
extern "C" void kernel_launch(void* const* d_in, const int* in_sizes, int n_in,
                              void* d_out, int out_size)
{
    const float* x0   = (const float*)d_in[0];
    const int*   eidx = (const int*)d_in[2];
    const int    E    = in_sizes[2] / 2;
    float*       out  = (float*)d_out;

    const int* src = eidx;
    const int* dst = eidx + E;

    float *xl, *xr, *b0, *b1, *e, *alpha;
    int *cnt, *rowptr, *cursor, *ceid, *csrc;
    cudaGetSymbolAddress((void**)&xl,     g_xl);
    cudaGetSymbolAddress((void**)&xr,     g_xr);
    cudaGetSymbolAddress((void**)&b0,     g_buf0);
    cudaGetSymbolAddress((void**)&b1,     g_buf1);
    cudaGetSymbolAddress((void**)&e,      g_e);
    cudaGetSymbolAddress((void**)&alpha,  g_alpha);
    cudaGetSymbolAddress((void**)&cnt,    g_cnt);
    cudaGetSymbolAddress((void**)&rowptr, g_rowptr);
    cudaGetSymbolAddress((void**)&cursor, g_cursor);
    cudaGetSymbolAddress((void**)&ceid,   g_ceid);
    cudaGetSymbolAddress((void**)&csrc,   g_csrc);

    zero_cnt_kernel<<<(NSEG + 255) / 256, 256>>>(cnt);
    hist_kernel<<<(E + 255) / 256, 256>>>(dst, cnt, E);
    scan8192_kernel<<<1, 1024>>>(cnt, rowptr, cursor);
    scatter_kernel<<<(E + 255) / 256, 256>>>(src, dst, cursor, ceid, csrc, E);

    const float* xin = x0;
    float* outs[3] = { b0, b1, out };
    for (int L = 0; L < 3; L++) {
        const int base = 3 + 6 * L;
        const float* Wl   = (const float*)d_in[base + 0];
        const float* bl   = (const float*)d_in[base + 1];
        const float* Wr   = (const float*)d_in[base + 2];
        const float* br   = (const float*)d_in[base + 3];
        const float* avec = (const float*)d_in[base + 4];
        const float* bias = (const float*)d_in[base + 5];

        dim3 gg(HDIM / 128, NSEG / 128, 2);
        gemm_tf32_kernel<<<gg, 256>>>(xin, Wl, bl, xl, Wr, br, xr);
        edge_score_kernel<<<(E + 7) / 8, 256>>>(xl, xr, avec, src, dst, e, E);
        softmax_kernel<<<(NSEG + 7) / 8, 256>>>(e, rowptr, ceid, alpha);
        aggregate_kernel<<<NSEG, 128>>>(xl, alpha, rowptr, csrc, bias, outs[L]);

        xin = outs[L];
    }
}

// round 4
// speedup vs baseline: 2.4764x; 1.0920x over previous
#include <cuda_runtime.h>
#include <cuda_bf16.h>
#include <math.h>
#include <stdint.h>

#define NSEG 8192
#define HDIM 512
#define MAXE 262144

// ---------------- device scratch ----------------
__device__ float g_xl[NSEG * HDIM];
__device__ float g_xr[NSEG * HDIM];
__device__ float g_buf0[NSEG * HDIM];
__device__ float g_buf1[NSEG * HDIM];
__device__ int   g_cnt[NSEG];
__device__ int   g_rowptr[NSEG + 1];
__device__ int   g_cursor[NSEG];
__device__ int   g_csrc[MAXE];

__device__ __forceinline__ float to_tf32(float x) {
    float r;
    asm("cvt.rna.tf32.f32 %0, %1;" : "=f"(r) : "f"(x));
    return r;
}
__device__ __forceinline__ uint32_t smem_u32(const void* p) {
    uint32_t a;
    asm("{ .reg .u64 t; cvta.to.shared.u64 t, %1; cvt.u32.u64 %0, t; }" : "=r"(a) : "l"(p));
    return a;
}
__device__ __forceinline__ void cp16(uint32_t dst, const void* src) {
    asm volatile("cp.async.cg.shared.global [%0], [%1], 16;" :: "r"(dst), "l"(src));
}

// ============ GEMM v3: Y = X@W + b, tf32 mma.sync, cp.async 2-stage ============
// Block tile 128(M) x 256(N), BK=16, 8 warps (warpR 0..1 x warpC 0..3), warp tile 64x64.
// Smem (floats): A stage 128x20 (pad), B stage 16x264 (pad).
#define A_STG 2560          // floats per A stage (128*20)
#define B_STG 4224          // floats per B stage (16*264)
#define SMEM_GEMM_BYTES ((2 * A_STG + 2 * B_STG) * 4)

__global__ __launch_bounds__(256, 1)
void gemm_tc3(const float* __restrict__ X,
              const float* __restrict__ W0, const float* __restrict__ b0, float* __restrict__ Y0,
              const float* __restrict__ W1, const float* __restrict__ b1, float* __restrict__ Y1)
{
    const float* W    = blockIdx.z ? W1 : W0;
    const float* bias = blockIdx.z ? b1 : b0;
    float*       Y    = blockIdx.z ? Y1 : Y0;

    extern __shared__ float sm[];
    const uint32_t smb = smem_u32(sm);

    const int tid  = threadIdx.x;
    const int warp = tid >> 5;
    const int lane = tid & 31;
    const int warpR = warp & 1;       // 0..1 -> 64-row slab
    const int warpC = warp >> 1;      // 0..3 -> 64-col slab
    const int rowBase = blockIdx.y * 128;
    const int colBase = blockIdx.x * 256;
    const int qr = lane >> 2;         // 0..7
    const int qc = lane & 3;          // 0..3

    float acc[4][8][4];
#pragma unroll
    for (int i = 0; i < 4; i++)
#pragma unroll
        for (int j = 0; j < 8; j++)
#pragma unroll
            for (int r = 0; r < 4; r++) acc[i][j][r] = 0.f;

    // ---- async tile issue ----
    auto issue = [&](int t) {
        const int s = t & 1;
        const int k0g = t * 16;
        const uint32_t aBase = smb + (s ? A_STG * 4 : 0);
        const uint32_t bBase = smb + (2 * A_STG + (s ? B_STG : 0)) * 4;
        // A: 128 rows x 16 k -> 512 float4
#pragma unroll
        for (int i = 0; i < 2; i++) {
            const int idx = tid + 256 * i;
            const int r = idx >> 2;
            const int c4 = (idx & 3) * 4;
            cp16(aBase + (uint32_t)(r * 20 + c4) * 4,
                 X + (size_t)(rowBase + r) * 512 + k0g + c4);
        }
        // B: 16 k x 256 n -> 1024 float4
#pragma unroll
        for (int i = 0; i < 4; i++) {
            const int idx = tid + 256 * i;
            const int r = idx >> 6;
            const int c4 = (idx & 63) * 4;
            cp16(bBase + (uint32_t)(r * 264 + c4) * 4,
                 W + (size_t)(k0g + r) * 512 + colBase + c4);
        }
        asm volatile("cp.async.commit_group;" ::: "memory");
    };

    issue(0);

    for (int t = 0; t < 32; t++) {
        if (t < 31) {
            issue(t + 1);
            asm volatile("cp.async.wait_group 1;" ::: "memory");
        } else {
            asm volatile("cp.async.wait_group 0;" ::: "memory");
        }
        __syncthreads();

        const int s = t & 1;
        const float* A = sm + (s ? A_STG : 0);
        const float* B = sm + 2 * A_STG + (s ? B_STG : 0);

#pragma unroll
        for (int ks = 0; ks < 2; ks++) {
            const int k0 = ks * 8;
            uint32_t a[4][4], b[8][2];
#pragma unroll
            for (int mt = 0; mt < 4; mt++) {
                const int m0 = warpR * 64 + mt * 16;
                a[mt][0] = __float_as_uint(to_tf32(A[(m0 + qr    ) * 20 + k0 + qc    ]));
                a[mt][1] = __float_as_uint(to_tf32(A[(m0 + qr + 8) * 20 + k0 + qc    ]));
                a[mt][2] = __float_as_uint(to_tf32(A[(m0 + qr    ) * 20 + k0 + qc + 4]));
                a[mt][3] = __float_as_uint(to_tf32(A[(m0 + qr + 8) * 20 + k0 + qc + 4]));
            }
#pragma unroll
            for (int nt = 0; nt < 8; nt++) {
                const int n0 = warpC * 64 + nt * 8;
                b[nt][0] = __float_as_uint(to_tf32(B[(k0 + qc    ) * 264 + n0 + qr]));
                b[nt][1] = __float_as_uint(to_tf32(B[(k0 + qc + 4) * 264 + n0 + qr]));
            }
#pragma unroll
            for (int mt = 0; mt < 4; mt++)
#pragma unroll
                for (int nt = 0; nt < 8; nt++) {
                    asm volatile(
                        "mma.sync.aligned.m16n8k8.row.col.f32.tf32.tf32.f32 "
                        "{%0,%1,%2,%3}, {%4,%5,%6,%7}, {%8,%9}, {%0,%1,%2,%3};"
                        : "+f"(acc[mt][nt][0]), "+f"(acc[mt][nt][1]),
                          "+f"(acc[mt][nt][2]), "+f"(acc[mt][nt][3])
                        : "r"(a[mt][0]), "r"(a[mt][1]), "r"(a[mt][2]), "r"(a[mt][3]),
                          "r"(b[nt][0]), "r"(b[nt][1]));
                }
        }
        __syncthreads();
    }

    // epilogue
#pragma unroll
    for (int mt = 0; mt < 4; mt++) {
#pragma unroll
        for (int nt = 0; nt < 8; nt++) {
            const int col = colBase + warpC * 64 + nt * 8 + qc * 2;
            const float bx = bias[col], by = bias[col + 1];
            const int r0 = rowBase + warpR * 64 + mt * 16 + qr;
            float2 v0 = make_float2(acc[mt][nt][0] + bx, acc[mt][nt][1] + by);
            float2 v1 = make_float2(acc[mt][nt][2] + bx, acc[mt][nt][3] + by);
            *(float2*)(Y + (size_t)r0 * 512 + col)       = v0;
            *(float2*)(Y + (size_t)(r0 + 8) * 512 + col) = v1;
        }
    }
}

// ---------------- CSR build (by dst; csrc only) ----------------
__global__ void zero_cnt_kernel(int* __restrict__ cnt) {
    int i = blockIdx.x * blockDim.x + threadIdx.x;
    if (i < NSEG) cnt[i] = 0;
}
__global__ void hist_kernel(const int* __restrict__ dst, int* __restrict__ cnt, int E) {
    int k = blockIdx.x * blockDim.x + threadIdx.x;
    if (k < E) atomicAdd(&cnt[dst[k]], 1);
}
__global__ void scan8192_kernel(const int* __restrict__ cnt, int* __restrict__ rowptr,
                                int* __restrict__ cursor)
{
    __shared__ int sums[1024];
    const int t = threadIdx.x;
    const int base = t * 8;
    int local[8];
    int s = 0;
#pragma unroll
    for (int j = 0; j < 8; j++) { local[j] = s; s += cnt[base + j]; }
    sums[t] = s;
    __syncthreads();
    for (int off = 1; off < 1024; off <<= 1) {
        int v = (t >= off) ? sums[t - off] : 0;
        __syncthreads();
        sums[t] += v;
        __syncthreads();
    }
    const int excl = (t == 0) ? 0 : sums[t - 1];
#pragma unroll
    for (int j = 0; j < 8; j++) {
        int v = excl + local[j];
        rowptr[base + j] = v;
        cursor[base + j] = v;
    }
    if (t == 1023) rowptr[NSEG] = sums[1023];
}
__global__ void scatter_kernel(const int* __restrict__ src, const int* __restrict__ dst,
                               int* __restrict__ cursor, int* __restrict__ csrc, int E)
{
    int k = blockIdx.x * blockDim.x + threadIdx.x;
    if (k < E) {
        int p = atomicAdd(&cursor[dst[k]], 1);
        csrc[p] = src[k];
    }
}

// ============ fused edge phase: score + online softmax + aggregate ============
// One block (128 thr, 4 warps) per dst node. Warp-per-edge, flash-style online softmax.
__device__ __forceinline__ float lrelu(float v) { return v > 0.f ? v : 0.2f * v; }

__global__ __launch_bounds__(128)
void fused_edge_kernel(const float* __restrict__ xl, const float* __restrict__ xr,
                       const float* __restrict__ a,
                       const int* __restrict__ rowptr, const int* __restrict__ csrc,
                       const float* __restrict__ bias, float* __restrict__ out)
{
    __shared__ float s_xr[HDIM];
    __shared__ float s_a[HDIM];
    __shared__ float s_m[4], s_s[4];
    __shared__ float s_acc[4][HDIM];

    const int node = blockIdx.x;
    const int tid  = threadIdx.x;
    const int warp = tid >> 5;
    const int lane = tid & 31;

    ((float4*)s_xr)[tid] = ((const float4*)(xr + (size_t)node * HDIM))[tid];
    ((float4*)s_a)[tid]  = ((const float4*)a)[tid];
    __syncthreads();

    float4 xrv[4], av[4];
#pragma unroll
    for (int c = 0; c < 4; c++) {
        xrv[c] = ((const float4*)s_xr)[c * 32 + lane];
        av[c]  = ((const float4*)s_a)[c * 32 + lane];
    }

    const int s0 = rowptr[node], s1 = rowptr[node + 1];
    float m = -INFINITY, ssum = 0.f;
    float4 accv[4];
#pragma unroll
    for (int c = 0; c < 4; c++) accv[c] = make_float4(0.f, 0.f, 0.f, 0.f);

    for (int j = s0 + warp; j < s1; j += 4) {
        const int sj = csrc[j];
        const float4* r4 = (const float4*)(xl + (size_t)sj * HDIM);
        float4 v[4];
#pragma unroll
        for (int c = 0; c < 4; c++) v[c] = r4[c * 32 + lane];

        float p = 0.f;
#pragma unroll
        for (int c = 0; c < 4; c++) {
            p = fmaf(av[c].x, lrelu(v[c].x + xrv[c].x), p);
            p = fmaf(av[c].y, lrelu(v[c].y + xrv[c].y), p);
            p = fmaf(av[c].z, lrelu(v[c].z + xrv[c].z), p);
            p = fmaf(av[c].w, lrelu(v[c].w + xrv[c].w), p);
        }
#pragma unroll
        for (int off = 16; off; off >>= 1) p += __shfl_xor_sync(0xFFFFFFFFu, p, off);

        const float mn = fmaxf(m, p);
        const float rs = __expf(m - mn);   // m=-inf -> 0
        const float w  = __expf(p - mn);
        ssum = ssum * rs + w;
#pragma unroll
        for (int c = 0; c < 4; c++) {
            accv[c].x = fmaf(w, v[c].x, accv[c].x * rs);
            accv[c].y = fmaf(w, v[c].y, accv[c].y * rs);
            accv[c].z = fmaf(w, v[c].z, accv[c].z * rs);
            accv[c].w = fmaf(w, v[c].w, accv[c].w * rs);
        }
        m = mn;
    }

    if (lane == 0) { s_m[warp] = m; s_s[warp] = ssum; }
    __syncthreads();

    const float M = fmaxf(fmaxf(s_m[0], s_m[1]), fmaxf(s_m[2], s_m[3]));
    float S = 0.f;
#pragma unroll
    for (int w = 0; w < 4; w++)
        S += (s_m[w] == -INFINITY) ? 0.f : s_s[w] * __expf(s_m[w] - M);
    const float scale = (m == -INFINITY) ? 0.f : __expf(m - M);

#pragma unroll
    for (int c = 0; c < 4; c++) {
        float4 t = accv[c];
        t.x *= scale; t.y *= scale; t.z *= scale; t.w *= scale;
        ((float4*)s_acc[warp])[c * 32 + lane] = t;
    }
    __syncthreads();

    const float inv = (M == -INFINITY) ? 0.f : 1.f / S;
    float4 o = ((const float4*)bias)[tid];
    float4 q0 = ((const float4*)s_acc[0])[tid];
    float4 q1 = ((const float4*)s_acc[1])[tid];
    float4 q2 = ((const float4*)s_acc[2])[tid];
    float4 q3 = ((const float4*)s_acc[3])[tid];
    o.x += (q0.x + q1.x + q2.x + q3.x) * inv;
    o.y += (q0.y + q1.y + q2.y + q3.y) * inv;
    o.z += (q0.z + q1.z + q2.z + q3.z) * inv;
    o.w += (q0.w + q1.w + q2.w + q3.w) * inv;
    ((float4*)(out + (size_t)node * HDIM))[tid] = o;
}

// ---------------- launch ----------------
extern "C" void kernel_launch(void* const* d_in, const int* in_sizes, int n_in,
                              void* d_out, int out_size)
{
    const float* x0   = (const float*)d_in[0];
    const int*   eidx = (const int*)d_in[2];
    const int    E    = in_sizes[2] / 2;
    float*       out  = (float*)d_out;

    const int* src = eidx;
    const int* dst = eidx + E;

    float *xl, *xr, *b0, *b1;
    int *cnt, *rowptr, *cursor, *csrc;
    cudaGetSymbolAddress((void**)&xl,     g_xl);
    cudaGetSymbolAddress((void**)&xr,     g_xr);
    cudaGetSymbolAddress((void**)&b0,     g_buf0);
    cudaGetSymbolAddress((void**)&b1,     g_buf1);
    cudaGetSymbolAddress((void**)&cnt,    g_cnt);
    cudaGetSymbolAddress((void**)&rowptr, g_rowptr);
    cudaGetSymbolAddress((void**)&cursor, g_cursor);
    cudaGetSymbolAddress((void**)&csrc,   g_csrc);

    cudaFuncSetAttribute(gemm_tc3, cudaFuncAttributeMaxDynamicSharedMemorySize, SMEM_GEMM_BYTES);

    zero_cnt_kernel<<<(NSEG + 255) / 256, 256>>>(cnt);
    hist_kernel<<<(E + 255) / 256, 256>>>(dst, cnt, E);
    scan8192_kernel<<<1, 1024>>>(cnt, rowptr, cursor);
    scatter_kernel<<<(E + 255) / 256, 256>>>(src, dst, cursor, csrc, E);

    const float* xin = x0;
    float* outs[3] = { b0, b1, out };
    for (int L = 0; L < 3; L++) {
        const int base = 3 + 6 * L;
        const float* Wl   = (const float*)d_in[base + 0];
        const float* bl   = (const float*)d_in[base + 1];
        const float* Wr   = (const float*)d_in[base + 2];
        const float* br   = (const float*)d_in[base + 3];
        const float* avec = (const float*)d_in[base + 4];
        const float* bias = (const float*)d_in[base + 5];

        dim3 gg(HDIM / 256, NSEG / 128, 2);
        gemm_tc3<<<gg, 256, SMEM_GEMM_BYTES>>>(xin, Wl, bl, xl, Wr, br, xr);
        fused_edge_kernel<<<NSEG, 128>>>(xl, xr, avec, rowptr, csrc, bias, outs[L]);

        xin = outs[L];
    }
}

// round 5
// speedup vs baseline: 2.7895x; 1.1265x over previous
#include <cuda_runtime.h>
#include <cuda_bf16.h>
#include <math.h>
#include <stdint.h>

#define NSEG 8192
#define HDIM 512
#define MAXE 262144

// ---------------- device scratch ----------------
__device__ float g_xl[NSEG * HDIM];
__device__ float g_xr[NSEG * HDIM];
__device__ float g_buf0[NSEG * HDIM];
__device__ float g_buf1[NSEG * HDIM];
__device__ int   g_cnt[NSEG];
__device__ int   g_rowptr[NSEG + 1];
__device__ int   g_cursor[NSEG];
__device__ int   g_csrc[MAXE];

__device__ __forceinline__ uint32_t smem_u32(const void* p) {
    uint32_t a;
    asm("{ .reg .u64 t; cvta.to.shared.u64 t, %1; cvt.u32.u64 %0, t; }" : "=r"(a) : "l"(p));
    return a;
}
__device__ __forceinline__ void cp16(uint32_t dst, const void* src) {
    asm volatile("cp.async.cg.shared.global [%0], [%1], 16;" :: "r"(dst), "l"(src));
}
// pack two fp32 -> fp16x2 (lo = first, hi = second)
__device__ __forceinline__ uint32_t f16x2(float lo, float hi) {
    uint32_t d;
    asm("cvt.rn.f16x2.f32 %0, %1, %2;" : "=r"(d) : "f"(hi), "f"(lo));
    return d;
}

// ============ GEMM v4: Y = X@W + b, fp16 mma.sync m16n8k16, cp.async 2-stage ============
// Block tile 128(M) x 256(N), BK=32, 8 warps (warpR 0..1 x warpC 0..3), warp tile 64x64.
// Smem fp32 stages: A 128x36 (pad), B 32x260 (pad).
#define A_STG 4608          // 128*36 floats
#define B_STG 8320          // 32*260 floats
#define SMEM_GEMM_BYTES ((2 * A_STG + 2 * B_STG) * 4)

__global__ __launch_bounds__(256, 1)
void gemm_tc4(const float* __restrict__ X,
              const float* __restrict__ W0, const float* __restrict__ b0, float* __restrict__ Y0,
              const float* __restrict__ W1, const float* __restrict__ b1, float* __restrict__ Y1)
{
    const float* W    = blockIdx.z ? W1 : W0;
    const float* bias = blockIdx.z ? b1 : b0;
    float*       Y    = blockIdx.z ? Y1 : Y0;

    extern __shared__ float sm[];
    const uint32_t smb = smem_u32(sm);

    const int tid  = threadIdx.x;
    const int warp = tid >> 5;
    const int lane = tid & 31;
    const int warpR = warp & 1;
    const int warpC = warp >> 1;
    const int rowBase = blockIdx.y * 128;
    const int colBase = blockIdx.x * 256;
    const int qr = lane >> 2;
    const int qc = lane & 3;

    float acc[4][8][4];
#pragma unroll
    for (int i = 0; i < 4; i++)
#pragma unroll
        for (int j = 0; j < 8; j++)
#pragma unroll
            for (int r = 0; r < 4; r++) acc[i][j][r] = 0.f;

    auto issue = [&](int t) {
        const int s = t & 1;
        const int k0g = t * 32;
        const uint32_t aBase = smb + (s ? A_STG * 4 : 0);
        const uint32_t bBase = smb + (2 * A_STG + (s ? B_STG : 0)) * 4;
        // A: 128 rows x 32 k -> 1024 float4
#pragma unroll
        for (int i = 0; i < 4; i++) {
            const int idx = tid + 256 * i;
            const int r = idx >> 3;
            const int c4 = (idx & 7) * 4;
            cp16(aBase + (uint32_t)(r * 36 + c4) * 4,
                 X + (size_t)(rowBase + r) * 512 + k0g + c4);
        }
        // B: 32 k x 256 n -> 2048 float4
#pragma unroll
        for (int i = 0; i < 8; i++) {
            const int idx = tid + 256 * i;
            const int r = idx >> 6;
            const int c4 = (idx & 63) * 4;
            cp16(bBase + (uint32_t)(r * 260 + c4) * 4,
                 W + (size_t)(k0g + r) * 512 + colBase + c4);
        }
        asm volatile("cp.async.commit_group;" ::: "memory");
    };

    issue(0);

    for (int t = 0; t < 16; t++) {
        if (t < 15) {
            issue(t + 1);
            asm volatile("cp.async.wait_group 1;" ::: "memory");
        } else {
            asm volatile("cp.async.wait_group 0;" ::: "memory");
        }
        __syncthreads();

        const int s = t & 1;
        const float* A = sm + (s ? A_STG : 0);
        const float* B = sm + 2 * A_STG + (s ? B_STG : 0);

#pragma unroll
        for (int ks = 0; ks < 2; ks++) {
            const int k0 = ks * 16;
            uint32_t a[4][4], b[8][2];
#pragma unroll
            for (int mt = 0; mt < 4; mt++) {
                const int m0 = warpR * 64 + mt * 16;
                float2 lo0 = *(const float2*)&A[(m0 + qr    ) * 36 + k0 + 2 * qc    ];
                float2 lo1 = *(const float2*)&A[(m0 + qr + 8) * 36 + k0 + 2 * qc    ];
                float2 hi0 = *(const float2*)&A[(m0 + qr    ) * 36 + k0 + 2 * qc + 8];
                float2 hi1 = *(const float2*)&A[(m0 + qr + 8) * 36 + k0 + 2 * qc + 8];
                a[mt][0] = f16x2(lo0.x, lo0.y);
                a[mt][1] = f16x2(lo1.x, lo1.y);
                a[mt][2] = f16x2(hi0.x, hi0.y);
                a[mt][3] = f16x2(hi1.x, hi1.y);
            }
#pragma unroll
            for (int nt = 0; nt < 8; nt++) {
                const int n0 = warpC * 64 + nt * 8;
                b[nt][0] = f16x2(B[(k0 + 2 * qc    ) * 260 + n0 + qr],
                                 B[(k0 + 2 * qc + 1) * 260 + n0 + qr]);
                b[nt][1] = f16x2(B[(k0 + 2 * qc + 8) * 260 + n0 + qr],
                                 B[(k0 + 2 * qc + 9) * 260 + n0 + qr]);
            }
#pragma unroll
            for (int mt = 0; mt < 4; mt++)
#pragma unroll
                for (int nt = 0; nt < 8; nt++) {
                    asm volatile(
                        "mma.sync.aligned.m16n8k16.row.col.f32.f16.f16.f32 "
                        "{%0,%1,%2,%3}, {%4,%5,%6,%7}, {%8,%9}, {%0,%1,%2,%3};"
                        : "+f"(acc[mt][nt][0]), "+f"(acc[mt][nt][1]),
                          "+f"(acc[mt][nt][2]), "+f"(acc[mt][nt][3])
                        : "r"(a[mt][0]), "r"(a[mt][1]), "r"(a[mt][2]), "r"(a[mt][3]),
                          "r"(b[nt][0]), "r"(b[nt][1]));
                }
        }
        __syncthreads();
    }

    // epilogue: + bias
#pragma unroll
    for (int mt = 0; mt < 4; mt++) {
#pragma unroll
        for (int nt = 0; nt < 8; nt++) {
            const int col = colBase + warpC * 64 + nt * 8 + qc * 2;
            const float bx = bias[col], by = bias[col + 1];
            const int r0 = rowBase + warpR * 64 + mt * 16 + qr;
            float2 v0 = make_float2(acc[mt][nt][0] + bx, acc[mt][nt][1] + by);
            float2 v1 = make_float2(acc[mt][nt][2] + bx, acc[mt][nt][3] + by);
            *(float2*)(Y + (size_t)r0 * 512 + col)       = v0;
            *(float2*)(Y + (size_t)(r0 + 8) * 512 + col) = v1;
        }
    }
}

// ---------------- CSR build (by dst; csrc only) ----------------
__global__ void zero_cnt_kernel(int* __restrict__ cnt) {
    int i = blockIdx.x * blockDim.x + threadIdx.x;
    if (i < NSEG) cnt[i] = 0;
}
__global__ void hist_kernel(const int* __restrict__ dst, int* __restrict__ cnt, int E) {
    int k = blockIdx.x * blockDim.x + threadIdx.x;
    if (k < E) atomicAdd(&cnt[dst[k]], 1);
}
__global__ void scan8192_kernel(const int* __restrict__ cnt, int* __restrict__ rowptr,
                                int* __restrict__ cursor)
{
    __shared__ int sums[1024];
    const int t = threadIdx.x;
    const int base = t * 8;
    int local[8];
    int s = 0;
#pragma unroll
    for (int j = 0; j < 8; j++) { local[j] = s; s += cnt[base + j]; }
    sums[t] = s;
    __syncthreads();
    for (int off = 1; off < 1024; off <<= 1) {
        int v = (t >= off) ? sums[t - off] : 0;
        __syncthreads();
        sums[t] += v;
        __syncthreads();
    }
    const int excl = (t == 0) ? 0 : sums[t - 1];
#pragma unroll
    for (int j = 0; j < 8; j++) {
        int v = excl + local[j];
        rowptr[base + j] = v;
        cursor[base + j] = v;
    }
    if (t == 1023) rowptr[NSEG] = sums[1023];
}
__global__ void scatter_kernel(const int* __restrict__ src, const int* __restrict__ dst,
                               int* __restrict__ cursor, int* __restrict__ csrc, int E)
{
    int k = blockIdx.x * blockDim.x + threadIdx.x;
    if (k < E) {
        int p = atomicAdd(&cursor[dst[k]], 1);
        csrc[p] = src[k];
    }
}

// ============ fused edge phase: score + online softmax + aggregate ============
__device__ __forceinline__ float lrelu(float v) { return v > 0.f ? v : 0.2f * v; }

__global__ __launch_bounds__(128)
void fused_edge_kernel(const float* __restrict__ xl, const float* __restrict__ xr,
                       const float* __restrict__ a,
                       const int* __restrict__ rowptr, const int* __restrict__ csrc,
                       const float* __restrict__ bias, float* __restrict__ out)
{
    __shared__ float s_xr[HDIM];
    __shared__ float s_a[HDIM];
    __shared__ float s_m[4], s_s[4];
    __shared__ float s_acc[4][HDIM];

    const int node = blockIdx.x;
    const int tid  = threadIdx.x;
    const int warp = tid >> 5;
    const int lane = tid & 31;

    ((float4*)s_xr)[tid] = ((const float4*)(xr + (size_t)node * HDIM))[tid];
    ((float4*)s_a)[tid]  = ((const float4*)a)[tid];
    __syncthreads();

    float4 xrv[4], av[4];
#pragma unroll
    for (int c = 0; c < 4; c++) {
        xrv[c] = ((const float4*)s_xr)[c * 32 + lane];
        av[c]  = ((const float4*)s_a)[c * 32 + lane];
    }

    const int s0 = rowptr[node], s1 = rowptr[node + 1];
    float m = -INFINITY, ssum = 0.f;
    float4 accv[4];
#pragma unroll
    for (int c = 0; c < 4; c++) accv[c] = make_float4(0.f, 0.f, 0.f, 0.f);

    for (int j = s0 + warp; j < s1; j += 4) {
        const int sj = csrc[j];
        const float4* r4 = (const float4*)(xl + (size_t)sj * HDIM);
        float4 v[4];
#pragma unroll
        for (int c = 0; c < 4; c++) v[c] = r4[c * 32 + lane];

        float p = 0.f;
#pragma unroll
        for (int c = 0; c < 4; c++) {
            p = fmaf(av[c].x, lrelu(v[c].x + xrv[c].x), p);
            p = fmaf(av[c].y, lrelu(v[c].y + xrv[c].y), p);
            p = fmaf(av[c].z, lrelu(v[c].z + xrv[c].z), p);
            p = fmaf(av[c].w, lrelu(v[c].w + xrv[c].w), p);
        }
#pragma unroll
        for (int off = 16; off; off >>= 1) p += __shfl_xor_sync(0xFFFFFFFFu, p, off);

        const float mn = fmaxf(m, p);
        const float rs = __expf(m - mn);
        const float w  = __expf(p - mn);
        ssum = ssum * rs + w;
#pragma unroll
        for (int c = 0; c < 4; c++) {
            accv[c].x = fmaf(w, v[c].x, accv[c].x * rs);
            accv[c].y = fmaf(w, v[c].y, accv[c].y * rs);
            accv[c].z = fmaf(w, v[c].z, accv[c].z * rs);
            accv[c].w = fmaf(w, v[c].w, accv[c].w * rs);
        }
        m = mn;
    }

    if (lane == 0) { s_m[warp] = m; s_s[warp] = ssum; }
    __syncthreads();

    const float M = fmaxf(fmaxf(s_m[0], s_m[1]), fmaxf(s_m[2], s_m[3]));
    float S = 0.f;
#pragma unroll
    for (int w = 0; w < 4; w++)
        S += (s_m[w] == -INFINITY) ? 0.f : s_s[w] * __expf(s_m[w] - M);
    const float scale = (m == -INFINITY) ? 0.f : __expf(m - M);

#pragma unroll
    for (int c = 0; c < 4; c++) {
        float4 t = accv[c];
        t.x *= scale; t.y *= scale; t.z *= scale; t.w *= scale;
        ((float4*)s_acc[warp])[c * 32 + lane] = t;
    }
    __syncthreads();

    const float inv = (M == -INFINITY) ? 0.f : 1.f / S;
    float4 o = ((const float4*)bias)[tid];
    float4 q0 = ((const float4*)s_acc[0])[tid];
    float4 q1 = ((const float4*)s_acc[1])[tid];
    float4 q2 = ((const float4*)s_acc[2])[tid];
    float4 q3 = ((const float4*)s_acc[3])[tid];
    o.x += (q0.x + q1.x + q2.x + q3.x) * inv;
    o.y += (q0.y + q1.y + q2.y + q3.y) * inv;
    o.z += (q0.z + q1.z + q2.z + q3.z) * inv;
    o.w += (q0.w + q1.w + q2.w + q3.w) * inv;
    ((float4*)(out + (size_t)node * HDIM))[tid] = o;
}

// ---------------- launch ----------------
extern "C" void kernel_launch(void* const* d_in, const int* in_sizes, int n_in,
                              void* d_out, int out_size)
{
    const float* x0   = (const float*)d_in[0];
    const int*   eidx = (const int*)d_in[2];
    const int    E    = in_sizes[2] / 2;
    float*       out  = (float*)d_out;

    const int* src = eidx;
    const int* dst = eidx + E;

    float *xl, *xr, *b0, *b1;
    int *cnt, *rowptr, *cursor, *csrc;
    cudaGetSymbolAddress((void**)&xl,     g_xl);
    cudaGetSymbolAddress((void**)&xr,     g_xr);
    cudaGetSymbolAddress((void**)&b0,     g_buf0);
    cudaGetSymbolAddress((void**)&b1,     g_buf1);
    cudaGetSymbolAddress((void**)&cnt,    g_cnt);
    cudaGetSymbolAddress((void**)&rowptr, g_rowptr);
    cudaGetSymbolAddress((void**)&cursor, g_cursor);
    cudaGetSymbolAddress((void**)&csrc,   g_csrc);

    cudaFuncSetAttribute(gemm_tc4, cudaFuncAttributeMaxDynamicSharedMemorySize, SMEM_GEMM_BYTES);

    zero_cnt_kernel<<<(NSEG + 255) / 256, 256>>>(cnt);
    hist_kernel<<<(E + 255) / 256, 256>>>(dst, cnt, E);
    scan8192_kernel<<<1, 1024>>>(cnt, rowptr, cursor);
    scatter_kernel<<<(E + 255) / 256, 256>>>(src, dst, cursor, csrc, E);

    const float* xin = x0;
    float* outs[3] = { b0, b1, out };
    for (int L = 0; L < 3; L++) {
        const int base = 3 + 6 * L;
        const float* Wl   = (const float*)d_in[base + 0];
        const float* bl   = (const float*)d_in[base + 1];
        const float* Wr   = (const float*)d_in[base + 2];
        const float* br   = (const float*)d_in[base + 3];
        const float* avec = (const float*)d_in[base + 4];
        const float* bias = (const float*)d_in[base + 5];

        dim3 gg(HDIM / 256, NSEG / 128, 2);
        gemm_tc4<<<gg, 256, SMEM_GEMM_BYTES>>>(xin, Wl, bl, xl, Wr, br, xr);
        fused_edge_kernel<<<NSEG, 128>>>(xl, xr, avec, rowptr, csrc, bias, outs[L]);

        xin = outs[L];
    }
}

// round 6
// speedup vs baseline: 3.1799x; 1.1400x over previous
#include <cuda_runtime.h>
#include <cuda_fp16.h>
#include <math.h>
#include <stdint.h>

#define NSEG 8192
#define HDIM 512
#define MAXE 262144

// ---------------- device scratch ----------------
__device__ float  g_xl[NSEG * HDIM];
__device__ float  g_xr[NSEG * HDIM];
__device__ float  g_buf0[NSEG * HDIM];
__device__ float  g_buf1[NSEG * HDIM];
__device__ __half g_xh[NSEG * HDIM];          // fp16 copy of current layer input
__device__ __half g_wh[6 * HDIM * HDIM];      // fp16 copies of Wl1,Wr1,Wl2,Wr2,Wl3,Wr3
__device__ int    g_cnt[NSEG];
__device__ int    g_rowptr[NSEG + 1];
__device__ int    g_cursor[NSEG];
__device__ int    g_csrc[MAXE];

__device__ __forceinline__ uint32_t smem_u32(const void* p) {
    uint32_t a;
    asm("{ .reg .u64 t; cvta.to.shared.u64 t, %1; cvt.u32.u64 %0, t; }" : "=r"(a) : "l"(p));
    return a;
}
__device__ __forceinline__ void cp16(uint32_t dst, const void* src) {
    asm volatile("cp.async.cg.shared.global [%0], [%1], 16;" :: "r"(dst), "l"(src));
}
__device__ __forceinline__ uint32_t pack_h2(float lo, float hi) {
    uint32_t d;
    asm("cvt.rn.f16x2.f32 %0, %1, %2;" : "=r"(d) : "f"(hi), "f"(lo));
    return d;
}

// ---------------- fp32 -> fp16 conversion ----------------
__global__ void f2h_kernel(const float4* __restrict__ in, uint2* __restrict__ out, int n4) {
    int i = blockIdx.x * blockDim.x + threadIdx.x;
    if (i < n4) {
        float4 v = in[i];
        out[i] = make_uint2(pack_h2(v.x, v.y), pack_h2(v.z, v.w));
    }
}
// convert 6 weight matrices (each 512x512) into g_wh
__global__ void wconv_kernel(const float4* __restrict__ w0, const float4* __restrict__ w1,
                             const float4* __restrict__ w2, const float4* __restrict__ w3,
                             const float4* __restrict__ w4, const float4* __restrict__ w5,
                             uint2* __restrict__ out)
{
    const float4* ws[6] = { w0, w1, w2, w3, w4, w5 };
    const int m = blockIdx.y;
    const int i = blockIdx.x * blockDim.x + threadIdx.x;   // < 512*512/4
    float4 v = ws[m][i];
    out[(size_t)m * (HDIM * HDIM / 4) + i] = make_uint2(pack_h2(v.x, v.y), pack_h2(v.z, v.w));
}

// ============ GEMM v5: fp16 smem + ldmatrix + mma m16n8k16 ============
// Block 128(M) x 256(N), BK=32, 8 warps (2x4), warp tile 64x64.
// Smem halves: A stage [128][40], B stage [32][264].
#define A_STGH 5120          // 128*40 halves
#define B_STGH 8448          // 32*264 halves
#define SMEM_GEMM_BYTES ((2 * A_STGH + 2 * B_STGH) * 2)

__global__ __launch_bounds__(256, 1)
void gemm_tc5(const __half* __restrict__ Xh,
              const __half* __restrict__ Wh0, const float* __restrict__ b0, float* __restrict__ Y0,
              const __half* __restrict__ Wh1, const float* __restrict__ b1, float* __restrict__ Y1)
{
    const __half* W   = blockIdx.z ? Wh1 : Wh0;
    const float* bias = blockIdx.z ? b1 : b0;
    float*       Y    = blockIdx.z ? Y1 : Y0;

    extern __shared__ __half sh[];
    const uint32_t smb = smem_u32(sh);

    const int tid  = threadIdx.x;
    const int warp = tid >> 5;
    const int lane = tid & 31;
    const int warpR = warp & 1;
    const int warpC = warp >> 1;
    const int rowBase = blockIdx.y * 128;
    const int colBase = blockIdx.x * 256;
    const int qr = lane >> 2;
    const int qc = lane & 3;

    float acc[4][8][4];
#pragma unroll
    for (int i = 0; i < 4; i++)
#pragma unroll
        for (int j = 0; j < 8; j++)
#pragma unroll
            for (int r = 0; r < 4; r++) acc[i][j][r] = 0.f;

    auto issue = [&](int t) {
        const int s = t & 1;
        const int k0g = t * 32;
        const uint32_t aBase = smb + (s ? A_STGH * 2 : 0);
        const uint32_t bBase = smb + (2 * A_STGH + (s ? B_STGH : 0)) * 2;
        // A: 128 rows x 32 halves = 512 x 16B chunks; 2 per thread
#pragma unroll
        for (int i = 0; i < 2; i++) {
            const int idx = tid + 256 * i;
            const int r  = idx >> 2;
            const int c8 = (idx & 3) * 8;       // halves
            cp16(aBase + (uint32_t)(r * 40 + c8) * 2,
                 Xh + (size_t)(rowBase + r) * 512 + k0g + c8);
        }
        // B: 32 rows x 256 halves = 1024 x 16B chunks; 4 per thread
#pragma unroll
        for (int i = 0; i < 4; i++) {
            const int idx = tid + 256 * i;
            const int r  = idx >> 5;
            const int c8 = (idx & 31) * 8;
            cp16(bBase + (uint32_t)(r * 264 + c8) * 2,
                 W + (size_t)(k0g + r) * 512 + colBase + c8);
        }
        asm volatile("cp.async.commit_group;" ::: "memory");
    };

    issue(0);

    for (int t = 0; t < 16; t++) {
        if (t < 15) {
            issue(t + 1);
            asm volatile("cp.async.wait_group 1;" ::: "memory");
        } else {
            asm volatile("cp.async.wait_group 0;" ::: "memory");
        }
        __syncthreads();

        const int s = t & 1;
        const uint32_t aS = smb + (s ? A_STGH * 2 : 0);
        const uint32_t bS = smb + (2 * A_STGH + (s ? B_STGH : 0)) * 2;

#pragma unroll
        for (int ks = 0; ks < 2; ks++) {
            const int k0 = ks * 16;
            uint32_t a[4][4], b[4][4];
            // A fragments: one ldmatrix.x4 per mt
#pragma unroll
            for (int mt = 0; mt < 4; mt++) {
                const int m0 = warpR * 64 + mt * 16;
                const int row = m0 + (lane & 15);
                const int col = k0 + (lane >> 4) * 8;
                const uint32_t addr = aS + (uint32_t)(row * 40 + col) * 2;
                asm volatile("ldmatrix.sync.aligned.m8n8.x4.shared.b16 {%0,%1,%2,%3}, [%4];"
                             : "=r"(a[mt][0]), "=r"(a[mt][1]), "=r"(a[mt][2]), "=r"(a[mt][3])
                             : "r"(addr));
            }
            // B fragments: one ldmatrix.x4.trans per nt-pair
#pragma unroll
            for (int np = 0; np < 4; np++) {
                const int n0 = warpC * 64 + np * 16;
                const int row = k0 + (lane & 7) + ((lane >> 3) & 1) * 8;
                const int col = n0 + (lane >> 4) * 8;
                const uint32_t addr = bS + (uint32_t)(row * 264 + col) * 2;
                asm volatile("ldmatrix.sync.aligned.m8n8.x4.trans.shared.b16 {%0,%1,%2,%3}, [%4];"
                             : "=r"(b[np][0]), "=r"(b[np][1]), "=r"(b[np][2]), "=r"(b[np][3])
                             : "r"(addr));
            }
#pragma unroll
            for (int mt = 0; mt < 4; mt++)
#pragma unroll
                for (int nt = 0; nt < 8; nt++) {
                    const uint32_t bb0 = b[nt >> 1][(nt & 1) * 2 + 0];
                    const uint32_t bb1 = b[nt >> 1][(nt & 1) * 2 + 1];
                    asm volatile(
                        "mma.sync.aligned.m16n8k16.row.col.f32.f16.f16.f32 "
                        "{%0,%1,%2,%3}, {%4,%5,%6,%7}, {%8,%9}, {%0,%1,%2,%3};"
                        : "+f"(acc[mt][nt][0]), "+f"(acc[mt][nt][1]),
                          "+f"(acc[mt][nt][2]), "+f"(acc[mt][nt][3])
                        : "r"(a[mt][0]), "r"(a[mt][1]), "r"(a[mt][2]), "r"(a[mt][3]),
                          "r"(bb0), "r"(bb1));
                }
        }
        __syncthreads();
    }

    // epilogue: + bias
#pragma unroll
    for (int mt = 0; mt < 4; mt++) {
#pragma unroll
        for (int nt = 0; nt < 8; nt++) {
            const int col = colBase + warpC * 64 + nt * 8 + qc * 2;
            const float bx = bias[col], by = bias[col + 1];
            const int r0 = rowBase + warpR * 64 + mt * 16 + qr;
            float2 v0 = make_float2(acc[mt][nt][0] + bx, acc[mt][nt][1] + by);
            float2 v1 = make_float2(acc[mt][nt][2] + bx, acc[mt][nt][3] + by);
            *(float2*)(Y + (size_t)r0 * 512 + col)       = v0;
            *(float2*)(Y + (size_t)(r0 + 8) * 512 + col) = v1;
        }
    }
}

// ---------------- CSR build (by dst; csrc only) ----------------
__global__ void zero_cnt_kernel(int* __restrict__ cnt) {
    int i = blockIdx.x * blockDim.x + threadIdx.x;
    if (i < NSEG) cnt[i] = 0;
}
__global__ void hist_kernel(const int* __restrict__ dst, int* __restrict__ cnt, int E) {
    int k = blockIdx.x * blockDim.x + threadIdx.x;
    if (k < E) atomicAdd(&cnt[dst[k]], 1);
}
__global__ void scan8192_kernel(const int* __restrict__ cnt, int* __restrict__ rowptr,
                                int* __restrict__ cursor)
{
    __shared__ int sums[1024];
    const int t = threadIdx.x;
    const int base = t * 8;
    int local[8];
    int s = 0;
#pragma unroll
    for (int j = 0; j < 8; j++) { local[j] = s; s += cnt[base + j]; }
    sums[t] = s;
    __syncthreads();
    for (int off = 1; off < 1024; off <<= 1) {
        int v = (t >= off) ? sums[t - off] : 0;
        __syncthreads();
        sums[t] += v;
        __syncthreads();
    }
    const int excl = (t == 0) ? 0 : sums[t - 1];
#pragma unroll
    for (int j = 0; j < 8; j++) {
        int v = excl + local[j];
        rowptr[base + j] = v;
        cursor[base + j] = v;
    }
    if (t == 1023) rowptr[NSEG] = sums[1023];
}
__global__ void scatter_kernel(const int* __restrict__ src, const int* __restrict__ dst,
                               int* __restrict__ cursor, int* __restrict__ csrc, int E)
{
    int k = blockIdx.x * blockDim.x + threadIdx.x;
    if (k < E) {
        int p = atomicAdd(&cursor[dst[k]], 1);
        csrc[p] = src[k];
    }
}

// ============ fused edge phase ============
__device__ __forceinline__ float lrelu(float v) { return v > 0.f ? v : 0.2f * v; }

__global__ __launch_bounds__(128)
void fused_edge_kernel(const float* __restrict__ xl, const float* __restrict__ xr,
                       const float* __restrict__ a,
                       const int* __restrict__ rowptr, const int* __restrict__ csrc,
                       const float* __restrict__ bias, float* __restrict__ out)
{
    __shared__ float s_xr[HDIM];
    __shared__ float s_a[HDIM];
    __shared__ float s_m[4], s_s[4];
    __shared__ float s_acc[4][HDIM];

    const int node = blockIdx.x;
    const int tid  = threadIdx.x;
    const int warp = tid >> 5;
    const int lane = tid & 31;

    ((float4*)s_xr)[tid] = ((const float4*)(xr + (size_t)node * HDIM))[tid];
    ((float4*)s_a)[tid]  = ((const float4*)a)[tid];
    __syncthreads();

    float4 xrv[4], av[4];
#pragma unroll
    for (int c = 0; c < 4; c++) {
        xrv[c] = ((const float4*)s_xr)[c * 32 + lane];
        av[c]  = ((const float4*)s_a)[c * 32 + lane];
    }

    const int s0 = rowptr[node], s1 = rowptr[node + 1];
    float m = -INFINITY, ssum = 0.f;
    float4 accv[4];
#pragma unroll
    for (int c = 0; c < 4; c++) accv[c] = make_float4(0.f, 0.f, 0.f, 0.f);

    for (int j = s0 + warp; j < s1; j += 4) {
        const int sj = csrc[j];
        const float4* r4 = (const float4*)(xl + (size_t)sj * HDIM);
        float4 v[4];
#pragma unroll
        for (int c = 0; c < 4; c++) v[c] = r4[c * 32 + lane];

        float p = 0.f;
#pragma unroll
        for (int c = 0; c < 4; c++) {
            p = fmaf(av[c].x, lrelu(v[c].x + xrv[c].x), p);
            p = fmaf(av[c].y, lrelu(v[c].y + xrv[c].y), p);
            p = fmaf(av[c].z, lrelu(v[c].z + xrv[c].z), p);
            p = fmaf(av[c].w, lrelu(v[c].w + xrv[c].w), p);
        }
#pragma unroll
        for (int off = 16; off; off >>= 1) p += __shfl_xor_sync(0xFFFFFFFFu, p, off);

        const float mn = fmaxf(m, p);
        const float rs = __expf(m - mn);
        const float w  = __expf(p - mn);
        ssum = ssum * rs + w;
#pragma unroll
        for (int c = 0; c < 4; c++) {
            accv[c].x = fmaf(w, v[c].x, accv[c].x * rs);
            accv[c].y = fmaf(w, v[c].y, accv[c].y * rs);
            accv[c].z = fmaf(w, v[c].z, accv[c].z * rs);
            accv[c].w = fmaf(w, v[c].w, accv[c].w * rs);
        }
        m = mn;
    }

    if (lane == 0) { s_m[warp] = m; s_s[warp] = ssum; }
    __syncthreads();

    const float M = fmaxf(fmaxf(s_m[0], s_m[1]), fmaxf(s_m[2], s_m[3]));
    float S = 0.f;
#pragma unroll
    for (int w = 0; w < 4; w++)
        S += (s_m[w] == -INFINITY) ? 0.f : s_s[w] * __expf(s_m[w] - M);
    const float scale = (m == -INFINITY) ? 0.f : __expf(m - M);

#pragma unroll
    for (int c = 0; c < 4; c++) {
        float4 t = accv[c];
        t.x *= scale; t.y *= scale; t.z *= scale; t.w *= scale;
        ((float4*)s_acc[warp])[c * 32 + lane] = t;
    }
    __syncthreads();

    const float inv = (M == -INFINITY) ? 0.f : 1.f / S;
    float4 o = ((const float4*)bias)[tid];
    float4 q0 = ((const float4*)s_acc[0])[tid];
    float4 q1 = ((const float4*)s_acc[1])[tid];
    float4 q2 = ((const float4*)s_acc[2])[tid];
    float4 q3 = ((const float4*)s_acc[3])[tid];
    o.x += (q0.x + q1.x + q2.x + q3.x) * inv;
    o.y += (q0.y + q1.y + q2.y + q3.y) * inv;
    o.z += (q0.z + q1.z + q2.z + q3.z) * inv;
    o.w += (q0.w + q1.w + q2.w + q3.w) * inv;
    ((float4*)(out + (size_t)node * HDIM))[tid] = o;
}

// ---------------- launch ----------------
extern "C" void kernel_launch(void* const* d_in, const int* in_sizes, int n_in,
                              void* d_out, int out_size)
{
    const float* x0   = (const float*)d_in[0];
    const int*   eidx = (const int*)d_in[2];
    const int    E    = in_sizes[2] / 2;
    float*       out  = (float*)d_out;

    const int* src = eidx;
    const int* dst = eidx + E;

    float *xl, *xr, *b0, *b1;
    __half *xh, *wh;
    int *cnt, *rowptr, *cursor, *csrc;
    cudaGetSymbolAddress((void**)&xl,     g_xl);
    cudaGetSymbolAddress((void**)&xr,     g_xr);
    cudaGetSymbolAddress((void**)&b0,     g_buf0);
    cudaGetSymbolAddress((void**)&b1,     g_buf1);
    cudaGetSymbolAddress((void**)&xh,     g_xh);
    cudaGetSymbolAddress((void**)&wh,     g_wh);
    cudaGetSymbolAddress((void**)&cnt,    g_cnt);
    cudaGetSymbolAddress((void**)&rowptr, g_rowptr);
    cudaGetSymbolAddress((void**)&cursor, g_cursor);
    cudaGetSymbolAddress((void**)&csrc,   g_csrc);

    cudaFuncSetAttribute(gemm_tc5, cudaFuncAttributeMaxDynamicSharedMemorySize, SMEM_GEMM_BYTES);

    // CSR build
    zero_cnt_kernel<<<(NSEG + 255) / 256, 256>>>(cnt);
    hist_kernel<<<(E + 255) / 256, 256>>>(dst, cnt, E);
    scan8192_kernel<<<1, 1024>>>(cnt, rowptr, cursor);
    scatter_kernel<<<(E + 255) / 256, 256>>>(src, dst, cursor, csrc, E);

    // weights -> fp16 (Wl1,Wr1,Wl2,Wr2,Wl3,Wr3)
    {
        dim3 g(HDIM * HDIM / 4 / 256, 6);
        wconv_kernel<<<g, 256>>>(
            (const float4*)d_in[3], (const float4*)d_in[5],
            (const float4*)d_in[9], (const float4*)d_in[11],
            (const float4*)d_in[15], (const float4*)d_in[17],
            (uint2*)wh);
    }

    const int N4 = NSEG * HDIM / 4;
    const float* xin = x0;
    float* outs[3] = { b0, b1, out };
    for (int L = 0; L < 3; L++) {
        const int base = 3 + 6 * L;
        const float* bl   = (const float*)d_in[base + 1];
        const float* br   = (const float*)d_in[base + 3];
        const float* avec = (const float*)d_in[base + 4];
        const float* bias = (const float*)d_in[base + 5];
        const __half* whl = wh + (size_t)(2 * L)     * HDIM * HDIM;
        const __half* whr = wh + (size_t)(2 * L + 1) * HDIM * HDIM;

        f2h_kernel<<<(N4 + 255) / 256, 256>>>((const float4*)xin, (uint2*)xh, N4);

        dim3 gg(HDIM / 256, NSEG / 128, 2);
        gemm_tc5<<<gg, 256, SMEM_GEMM_BYTES>>>(xh, whl, bl, xl, whr, br, xr);
        fused_edge_kernel<<<NSEG, 128>>>(xl, xr, avec, rowptr, csrc, bias, outs[L]);

        xin = outs[L];
    }
}

// round 7
// speedup vs baseline: 3.2955x; 1.0364x over previous
#include <cuda_runtime.h>
#include <cuda_fp16.h>
#include <math.h>
#include <stdint.h>

#define NSEG 8192
#define HDIM 512
#define MAXE 262144

// ---------------- device scratch ----------------
__device__ __half g_xlh[NSEG * HDIM];         // xl in fp16 (GEMM z=0 output)
__device__ float  g_xr[NSEG * HDIM];          // xr fp32
__device__ float  g_buf0[NSEG * HDIM];
__device__ float  g_buf1[NSEG * HDIM];
__device__ __half g_xh[NSEG * HDIM];          // fp16 copy of current layer input
__device__ __half g_wh[6 * HDIM * HDIM];      // fp16 Wl1,Wr1,Wl2,Wr2,Wl3,Wr3
__device__ int    g_cnt[NSEG];
__device__ int    g_rowptr[NSEG + 1];
__device__ int    g_cursor[NSEG];
__device__ int    g_csrc[MAXE];

__device__ __forceinline__ uint32_t smem_u32(const void* p) {
    uint32_t a;
    asm("{ .reg .u64 t; cvta.to.shared.u64 t, %1; cvt.u32.u64 %0, t; }" : "=r"(a) : "l"(p));
    return a;
}
__device__ __forceinline__ void cp16(uint32_t dst, const void* src) {
    asm volatile("cp.async.cg.shared.global [%0], [%1], 16;" :: "r"(dst), "l"(src));
}
__device__ __forceinline__ uint32_t pack_h2(float lo, float hi) {
    uint32_t d;
    asm("cvt.rn.f16x2.f32 %0, %1, %2;" : "=r"(d) : "f"(hi), "f"(lo));
    return d;
}

// ---------------- conversions ----------------
__global__ void f2h_kernel(const float4* __restrict__ in, uint2* __restrict__ out, int n4) {
    int i = blockIdx.x * blockDim.x + threadIdx.x;
    if (i < n4) {
        float4 v = in[i];
        out[i] = make_uint2(pack_h2(v.x, v.y), pack_h2(v.z, v.w));
    }
}
__global__ void wconv_kernel(const float4* __restrict__ w0, const float4* __restrict__ w1,
                             const float4* __restrict__ w2, const float4* __restrict__ w3,
                             const float4* __restrict__ w4, const float4* __restrict__ w5,
                             uint2* __restrict__ out)
{
    const float4* ws[6] = { w0, w1, w2, w3, w4, w5 };
    const int m = blockIdx.y;
    const int i = blockIdx.x * blockDim.x + threadIdx.x;
    float4 v = ws[m][i];
    out[(size_t)m * (HDIM * HDIM / 4) + i] = make_uint2(pack_h2(v.x, v.y), pack_h2(v.z, v.w));
}

// ============ GEMM v6: fp16 smem + ldmatrix + mma m16n8k16, 3-stage cp.async ============
// Block 128(M) x 256(N), BK=32, 8 warps (2x4), warp tile 64x64.
// z=0: Y -> fp16 (xl); z=1: Y -> fp32 (xr).
#define A_STGH 5120          // 128*40 halves
#define B_STGH 8448          // 32*264 halves
#define STG_H  (A_STGH + B_STGH)
#define SMEM_GEMM_BYTES (3 * STG_H * 2)

__global__ __launch_bounds__(256, 1)
void gemm_tc6(const __half* __restrict__ Xh,
              const __half* __restrict__ Wh0, const float* __restrict__ b0, __half* __restrict__ Yh0,
              const __half* __restrict__ Wh1, const float* __restrict__ b1, float* __restrict__ Y1)
{
    const __half* W   = blockIdx.z ? Wh1 : Wh0;
    const float* bias = blockIdx.z ? b1 : b0;

    extern __shared__ __half sh[];
    const uint32_t smb = smem_u32(sh);

    const int tid  = threadIdx.x;
    const int warp = tid >> 5;
    const int lane = tid & 31;
    const int warpR = warp & 1;
    const int warpC = warp >> 1;
    const int rowBase = blockIdx.y * 128;
    const int colBase = blockIdx.x * 256;
    const int qr = lane >> 2;
    const int qc = lane & 3;

    float acc[4][8][4];
#pragma unroll
    for (int i = 0; i < 4; i++)
#pragma unroll
        for (int j = 0; j < 8; j++)
#pragma unroll
            for (int r = 0; r < 4; r++) acc[i][j][r] = 0.f;

    auto issue = [&](int t) {
        const int s = t % 3;
        const int k0g = t * 32;
        const uint32_t aBase = smb + (uint32_t)(s * STG_H) * 2;
        const uint32_t bBase = aBase + (uint32_t)A_STGH * 2;
#pragma unroll
        for (int i = 0; i < 2; i++) {
            const int idx = tid + 256 * i;
            const int r  = idx >> 2;
            const int c8 = (idx & 3) * 8;
            cp16(aBase + (uint32_t)(r * 40 + c8) * 2,
                 Xh + (size_t)(rowBase + r) * 512 + k0g + c8);
        }
#pragma unroll
        for (int i = 0; i < 4; i++) {
            const int idx = tid + 256 * i;
            const int r  = idx >> 5;
            const int c8 = (idx & 31) * 8;
            cp16(bBase + (uint32_t)(r * 264 + c8) * 2,
                 W + (size_t)(k0g + r) * 512 + colBase + c8);
        }
        asm volatile("cp.async.commit_group;" ::: "memory");
    };

    issue(0);
    issue(1);

    for (int t = 0; t < 16; t++) {
        if (t < 15) {
            asm volatile("cp.async.wait_group 1;" ::: "memory");
        } else {
            asm volatile("cp.async.wait_group 0;" ::: "memory");
        }
        __syncthreads();

        const int s = t % 3;
        const uint32_t aS = smb + (uint32_t)(s * STG_H) * 2;
        const uint32_t bS = aS + (uint32_t)A_STGH * 2;

#pragma unroll
        for (int ks = 0; ks < 2; ks++) {
            const int k0 = ks * 16;
            uint32_t a[4][4], b[4][4];
#pragma unroll
            for (int mt = 0; mt < 4; mt++) {
                const int m0 = warpR * 64 + mt * 16;
                const int row = m0 + (lane & 15);
                const int col = k0 + (lane >> 4) * 8;
                const uint32_t addr = aS + (uint32_t)(row * 40 + col) * 2;
                asm volatile("ldmatrix.sync.aligned.m8n8.x4.shared.b16 {%0,%1,%2,%3}, [%4];"
                             : "=r"(a[mt][0]), "=r"(a[mt][1]), "=r"(a[mt][2]), "=r"(a[mt][3])
                             : "r"(addr));
            }
#pragma unroll
            for (int np = 0; np < 4; np++) {
                const int n0 = warpC * 64 + np * 16;
                const int row = k0 + (lane & 7) + ((lane >> 3) & 1) * 8;
                const int col = n0 + (lane >> 4) * 8;
                const uint32_t addr = bS + (uint32_t)(row * 264 + col) * 2;
                asm volatile("ldmatrix.sync.aligned.m8n8.x4.trans.shared.b16 {%0,%1,%2,%3}, [%4];"
                             : "=r"(b[np][0]), "=r"(b[np][1]), "=r"(b[np][2]), "=r"(b[np][3])
                             : "r"(addr));
            }
#pragma unroll
            for (int mt = 0; mt < 4; mt++)
#pragma unroll
                for (int nt = 0; nt < 8; nt++) {
                    const uint32_t bb0 = b[nt >> 1][(nt & 1) * 2 + 0];
                    const uint32_t bb1 = b[nt >> 1][(nt & 1) * 2 + 1];
                    asm volatile(
                        "mma.sync.aligned.m16n8k16.row.col.f32.f16.f16.f32 "
                        "{%0,%1,%2,%3}, {%4,%5,%6,%7}, {%8,%9}, {%0,%1,%2,%3};"
                        : "+f"(acc[mt][nt][0]), "+f"(acc[mt][nt][1]),
                          "+f"(acc[mt][nt][2]), "+f"(acc[mt][nt][3])
                        : "r"(a[mt][0]), "r"(a[mt][1]), "r"(a[mt][2]), "r"(a[mt][3]),
                          "r"(bb0), "r"(bb1));
                }
        }
        if (t + 2 < 16) issue(t + 2);
    }

    // epilogue: + bias; z=0 -> fp16 xl, z=1 -> fp32 xr
    if (blockIdx.z == 0) {
#pragma unroll
        for (int mt = 0; mt < 4; mt++) {
#pragma unroll
            for (int nt = 0; nt < 8; nt++) {
                const int col = colBase + warpC * 64 + nt * 8 + qc * 2;
                const float bx = bias[col], by = bias[col + 1];
                const int r0 = rowBase + warpR * 64 + mt * 16 + qr;
                *(uint32_t*)(Yh0 + (size_t)r0 * 512 + col) =
                    pack_h2(acc[mt][nt][0] + bx, acc[mt][nt][1] + by);
                *(uint32_t*)(Yh0 + (size_t)(r0 + 8) * 512 + col) =
                    pack_h2(acc[mt][nt][2] + bx, acc[mt][nt][3] + by);
            }
        }
    } else {
#pragma unroll
        for (int mt = 0; mt < 4; mt++) {
#pragma unroll
            for (int nt = 0; nt < 8; nt++) {
                const int col = colBase + warpC * 64 + nt * 8 + qc * 2;
                const float bx = bias[col], by = bias[col + 1];
                const int r0 = rowBase + warpR * 64 + mt * 16 + qr;
                *(float2*)(Y1 + (size_t)r0 * 512 + col) =
                    make_float2(acc[mt][nt][0] + bx, acc[mt][nt][1] + by);
                *(float2*)(Y1 + (size_t)(r0 + 8) * 512 + col) =
                    make_float2(acc[mt][nt][2] + bx, acc[mt][nt][3] + by);
            }
        }
    }
}

// ---------------- CSR build ----------------
__global__ void zero_cnt_kernel(int* __restrict__ cnt) {
    int i = blockIdx.x * blockDim.x + threadIdx.x;
    if (i < NSEG) cnt[i] = 0;
}
__global__ void hist_kernel(const int* __restrict__ dst, int* __restrict__ cnt, int E) {
    int k = blockIdx.x * blockDim.x + threadIdx.x;
    if (k < E) atomicAdd(&cnt[dst[k]], 1);
}
__global__ void scan8192_kernel(const int* __restrict__ cnt, int* __restrict__ rowptr,
                                int* __restrict__ cursor)
{
    __shared__ int sums[1024];
    const int t = threadIdx.x;
    const int base = t * 8;
    int local[8];
    int s = 0;
#pragma unroll
    for (int j = 0; j < 8; j++) { local[j] = s; s += cnt[base + j]; }
    sums[t] = s;
    __syncthreads();
    for (int off = 1; off < 1024; off <<= 1) {
        int v = (t >= off) ? sums[t - off] : 0;
        __syncthreads();
        sums[t] += v;
        __syncthreads();
    }
    const int excl = (t == 0) ? 0 : sums[t - 1];
#pragma unroll
    for (int j = 0; j < 8; j++) {
        int v = excl + local[j];
        rowptr[base + j] = v;
        cursor[base + j] = v;
    }
    if (t == 1023) rowptr[NSEG] = sums[1023];
}
__global__ void scatter_kernel(const int* __restrict__ src, const int* __restrict__ dst,
                               int* __restrict__ cursor, int* __restrict__ csrc, int E)
{
    int k = blockIdx.x * blockDim.x + threadIdx.x;
    if (k < E) {
        int p = atomicAdd(&cursor[dst[k]], 1);
        csrc[p] = src[k];
    }
}

// ============ fused edge phase (xl in fp16) ============
__device__ __forceinline__ float lrelu(float v) { return v > 0.f ? v : 0.2f * v; }

__global__ __launch_bounds__(128)
void fused_edge2(const __half* __restrict__ xlh, const float* __restrict__ xr,
                 const float* __restrict__ a,
                 const int* __restrict__ rowptr, const int* __restrict__ csrc,
                 const float* __restrict__ bias,
                 float* __restrict__ out, __half* __restrict__ outh)
{
    __shared__ float s_xr[HDIM];
    __shared__ float s_a[HDIM];
    __shared__ float s_m[4], s_s[4];
    __shared__ float s_acc[4][HDIM];

    const int node = blockIdx.x;
    const int tid  = threadIdx.x;
    const int warp = tid >> 5;
    const int lane = tid & 31;

    ((float4*)s_xr)[tid] = ((const float4*)(xr + (size_t)node * HDIM))[tid];
    ((float4*)s_a)[tid]  = ((const float4*)a)[tid];
    __syncthreads();

    // per-lane element chunks: c in {0,1}, 16B fp16 chunk index c*32+lane -> elements 8*(c*32+lane)..+7
    float4 xrv[4], av[4];      // slot 2c+j  <-> elements 8*(c*32+lane)+4j..+3
#pragma unroll
    for (int c = 0; c < 2; c++)
#pragma unroll
        for (int j = 0; j < 2; j++) {
            xrv[2 * c + j] = ((const float4*)s_xr)[2 * (c * 32 + lane) + j];
            av[2 * c + j]  = ((const float4*)s_a)[2 * (c * 32 + lane) + j];
        }

    const int s0 = rowptr[node], s1 = rowptr[node + 1];
    float m = -INFINITY, ssum = 0.f;
    float4 accv[4];
#pragma unroll
    for (int c = 0; c < 4; c++) accv[c] = make_float4(0.f, 0.f, 0.f, 0.f);

    for (int j = s0 + warp; j < s1; j += 4) {
        const int sj = csrc[j];
        const uint4* r16 = (const uint4*)(xlh + (size_t)sj * HDIM);
        float4 v[4];
#pragma unroll
        for (int c = 0; c < 2; c++) {
            uint4 u = r16[c * 32 + lane];
            const __half2* h = (const __half2*)&u;
            float2 p0 = __half22float2(h[0]);
            float2 p1 = __half22float2(h[1]);
            float2 p2 = __half22float2(h[2]);
            float2 p3 = __half22float2(h[3]);
            v[2 * c + 0] = make_float4(p0.x, p0.y, p1.x, p1.y);
            v[2 * c + 1] = make_float4(p2.x, p2.y, p3.x, p3.y);
        }

        float p = 0.f;
#pragma unroll
        for (int c = 0; c < 4; c++) {
            p = fmaf(av[c].x, lrelu(v[c].x + xrv[c].x), p);
            p = fmaf(av[c].y, lrelu(v[c].y + xrv[c].y), p);
            p = fmaf(av[c].z, lrelu(v[c].z + xrv[c].z), p);
            p = fmaf(av[c].w, lrelu(v[c].w + xrv[c].w), p);
        }
#pragma unroll
        for (int off = 16; off; off >>= 1) p += __shfl_xor_sync(0xFFFFFFFFu, p, off);

        const float mn = fmaxf(m, p);
        const float rs = __expf(m - mn);
        const float w  = __expf(p - mn);
        ssum = ssum * rs + w;
#pragma unroll
        for (int c = 0; c < 4; c++) {
            accv[c].x = fmaf(w, v[c].x, accv[c].x * rs);
            accv[c].y = fmaf(w, v[c].y, accv[c].y * rs);
            accv[c].z = fmaf(w, v[c].z, accv[c].z * rs);
            accv[c].w = fmaf(w, v[c].w, accv[c].w * rs);
        }
        m = mn;
    }

    if (lane == 0) { s_m[warp] = m; s_s[warp] = ssum; }
    __syncthreads();

    const float M = fmaxf(fmaxf(s_m[0], s_m[1]), fmaxf(s_m[2], s_m[3]));
    float S = 0.f;
#pragma unroll
    for (int w = 0; w < 4; w++)
        S += (s_m[w] == -INFINITY) ? 0.f : s_s[w] * __expf(s_m[w] - M);
    const float scale = (m == -INFINITY) ? 0.f : __expf(m - M);

#pragma unroll
    for (int c = 0; c < 2; c++)
#pragma unroll
        for (int j = 0; j < 2; j++) {
            float4 t = accv[2 * c + j];
            t.x *= scale; t.y *= scale; t.z *= scale; t.w *= scale;
            ((float4*)s_acc[warp])[2 * (c * 32 + lane) + j] = t;
        }
    __syncthreads();

    const float inv = (M == -INFINITY) ? 0.f : 1.f / S;
    float4 o = ((const float4*)bias)[tid];
    float4 q0 = ((const float4*)s_acc[0])[tid];
    float4 q1 = ((const float4*)s_acc[1])[tid];
    float4 q2 = ((const float4*)s_acc[2])[tid];
    float4 q3 = ((const float4*)s_acc[3])[tid];
    o.x += (q0.x + q1.x + q2.x + q3.x) * inv;
    o.y += (q0.y + q1.y + q2.y + q3.y) * inv;
    o.z += (q0.z + q1.z + q2.z + q3.z) * inv;
    o.w += (q0.w + q1.w + q2.w + q3.w) * inv;
    ((float4*)(out + (size_t)node * HDIM))[tid] = o;
    ((uint2*)(outh + (size_t)node * HDIM))[tid] =
        make_uint2(pack_h2(o.x, o.y), pack_h2(o.z, o.w));
}

// ---------------- launch ----------------
extern "C" void kernel_launch(void* const* d_in, const int* in_sizes, int n_in,
                              void* d_out, int out_size)
{
    const float* x0   = (const float*)d_in[0];
    const int*   eidx = (const int*)d_in[2];
    const int    E    = in_sizes[2] / 2;
    float*       out  = (float*)d_out;

    const int* src = eidx;
    const int* dst = eidx + E;

    float *xr, *b0, *b1;
    __half *xlh, *xh, *wh;
    int *cnt, *rowptr, *cursor, *csrc;
    cudaGetSymbolAddress((void**)&xlh,    g_xlh);
    cudaGetSymbolAddress((void**)&xr,     g_xr);
    cudaGetSymbolAddress((void**)&b0,     g_buf0);
    cudaGetSymbolAddress((void**)&b1,     g_buf1);
    cudaGetSymbolAddress((void**)&xh,     g_xh);
    cudaGetSymbolAddress((void**)&wh,     g_wh);
    cudaGetSymbolAddress((void**)&cnt,    g_cnt);
    cudaGetSymbolAddress((void**)&rowptr, g_rowptr);
    cudaGetSymbolAddress((void**)&cursor, g_cursor);
    cudaGetSymbolAddress((void**)&csrc,   g_csrc);

    cudaFuncSetAttribute(gemm_tc6, cudaFuncAttributeMaxDynamicSharedMemorySize, SMEM_GEMM_BYTES);

    zero_cnt_kernel<<<(NSEG + 255) / 256, 256>>>(cnt);
    hist_kernel<<<(E + 255) / 256, 256>>>(dst, cnt, E);
    scan8192_kernel<<<1, 1024>>>(cnt, rowptr, cursor);
    scatter_kernel<<<(E + 255) / 256, 256>>>(src, dst, cursor, csrc, E);

    {
        dim3 g(HDIM * HDIM / 4 / 256, 6);
        wconv_kernel<<<g, 256>>>(
            (const float4*)d_in[3], (const float4*)d_in[5],
            (const float4*)d_in[9], (const float4*)d_in[11],
            (const float4*)d_in[15], (const float4*)d_in[17],
            (uint2*)wh);
    }

    const int N4 = NSEG * HDIM / 4;
    f2h_kernel<<<(N4 + 255) / 256, 256>>>((const float4*)x0, (uint2*)xh, N4);

    float* outs[3] = { b0, b1, out };
    for (int L = 0; L < 3; L++) {
        const int base = 3 + 6 * L;
        const float* bl   = (const float*)d_in[base + 1];
        const float* br   = (const float*)d_in[base + 3];
        const float* avec = (const float*)d_in[base + 4];
        const float* bias = (const float*)d_in[base + 5];
        const __half* whl = wh + (size_t)(2 * L)     * HDIM * HDIM;
        const __half* whr = wh + (size_t)(2 * L + 1) * HDIM * HDIM;

        dim3 gg(HDIM / 256, NSEG / 128, 2);
        gemm_tc6<<<gg, 256, SMEM_GEMM_BYTES>>>(xh, whl, bl, xlh, whr, br, xr);
        // fused edge: writes fp32 out and fp16 next-layer input (xh)
        fused_edge2<<<NSEG, 128>>>(xlh, xr, avec, rowptr, csrc, bias, outs[L], xh);
    }
}